// round 7
// baseline (speedup 1.0000x reference)
#include <cuda_runtime.h>
#include <cuda_bf16.h>
#include <cstdint>

#define BATCH     4096
#define FILTER    1024
#define RELC      19
#define RELD      1024
#define SLAB      (FILTER * RELC)          // 19456 floats per batch row
#define SLAB_B    (SLAB * 4)               // 77824 bytes
#define THREADS2  608                      // 19 * 32
#define KPT       32                       // f-chunks per thread

// Precomputed W[f][r] = sum_e U[f,e] * R[r,e], row-major [FILTER][RELC]
__device__ float W_global[SLAB];

// ---------------------------------------------------------------------------
// Kernel 1: W = U @ R^T.  One warp per f-row, 19 register accumulators,
// R stays L1-resident (76KB). Butterfly reduce with ILP across 19 chains.
// ---------------------------------------------------------------------------
__global__ void __launch_bounds__(128) compute_W_kernel(const float* __restrict__ U,
                                                        const float* __restrict__ R)
{
    int warp = threadIdx.x >> 5;
    int lane = threadIdx.x & 31;
    int f = blockIdx.x * 4 + warp;          // 256 blocks * 4 warps = 1024 rows

    const float4* u4 = reinterpret_cast<const float4*>(U + (size_t)f * RELD);
    float4 u[8];
#pragma unroll
    for (int k = 0; k < 8; k++) u[k] = u4[lane + 32 * k];

    const float4* R4 = reinterpret_cast<const float4*>(R);
    float acc[RELC];
#pragma unroll
    for (int r = 0; r < RELC; r++) acc[r] = 0.f;

#pragma unroll
    for (int k = 0; k < 8; k++) {
        float4 uk = u[k];
#pragma unroll
        for (int r = 0; r < RELC; r++) {
            float4 rv = R4[r * 256 + lane + 32 * k];
            acc[r] += uk.x * rv.x + uk.y * rv.y + uk.z * rv.z + uk.w * rv.w;
        }
    }

    // Butterfly reduce: 19 independent 5-step chains (good ILP)
#pragma unroll
    for (int o = 16; o > 0; o >>= 1) {
#pragma unroll
        for (int r = 0; r < RELC; r++)
            acc[r] += __shfl_xor_sync(0xFFFFFFFFu, acc[r], o);
    }

    if (lane == 0) {
#pragma unroll
        for (int r = 0; r < RELC; r++)
            W_global[f * RELC + r] = acc[r];
    }
}

// ---------------------------------------------------------------------------
// mbarrier / bulk-copy helpers
// ---------------------------------------------------------------------------
__device__ __forceinline__ void mbar_init(uint32_t mbar, uint32_t count) {
    asm volatile("mbarrier.init.shared.b64 [%0], %1;" :: "r"(mbar), "r"(count) : "memory");
}
__device__ __forceinline__ void mbar_expect_tx(uint32_t mbar, uint32_t bytes) {
    asm volatile("mbarrier.arrive.expect_tx.shared.b64 _, [%0], %1;"
                 :: "r"(mbar), "r"(bytes) : "memory");
}
__device__ __forceinline__ void bulk_g2s(uint32_t dst_smem, const void* src, uint32_t bytes,
                                         uint32_t mbar) {
    asm volatile("cp.async.bulk.shared::cta.global.mbarrier::complete_tx::bytes "
                 "[%0], [%1], %2, [%3];"
                 :: "r"(dst_smem), "l"(src), "r"(bytes), "r"(mbar) : "memory");
}
__device__ __forceinline__ void mbar_wait(uint32_t mbar, uint32_t parity) {
    uint32_t done;
    asm volatile(
        "{\n\t.reg .pred p;\n\t"
        "mbarrier.try_wait.parity.acquire.cta.shared::cta.b64 p, [%1], %2;\n\t"
        "selp.b32 %0, 1, 0, p;\n\t}"
        : "=r"(done) : "r"(mbar), "r"(parity) : "memory");
    if (!done) {
        asm volatile(
            "{\n\t.reg .pred P1;\n\t"
            "W_%=:\n\t"
            "mbarrier.try_wait.parity.acquire.cta.shared::cta.b64 P1, [%0], %1, 0x989680;\n\t"
            "@P1 bra.uni D_%=;\n\t"
            "bra.uni W_%=;\n\t"
            "D_%=:\n\t}"
            :: "r"(mbar), "r"(parity) : "memory");
    }
}

// ---------------------------------------------------------------------------
// Kernel 2: scores[b,r] = sum_f conv[b,f,r] * W[f,r]
// Persistent blocks. ONE cp.async.bulk per 76KB slab (no per-thread cp.async,
// no pre-compute __syncthreads — the mbarrier wait is the data barrier).
// Index identity: element (tid + 608*k) of a slab has fixed r = tid % 19,
// so per-thread work is linear smem reads vs 32 W registers.
// red[] is double-buffered so only one __syncthreads per iteration remains.
// ---------------------------------------------------------------------------
__global__ void __launch_bounds__(THREADS2, 1)
score_kernel(const float* __restrict__ conv, float* __restrict__ out)
{
    extern __shared__ float smem[];
    float* buf0 = smem;                         // 19456 floats
    float* buf1 = smem + SLAB;                  // 19456 floats
    float* red  = smem + 2 * SLAB;              // 2 * 608 floats (dbl-buffered)
    // mbarriers: 8-byte aligned region after red
    uint32_t sbase = (uint32_t)__cvta_generic_to_shared(smem);
    uint32_t mb0 = sbase + (2 * SLAB + 2 * THREADS2) * 4;
    uint32_t mb1 = mb0 + 8;
    uint32_t sbuf0 = sbase;
    uint32_t sbuf1 = sbase + SLAB * 4;

    const int tid = threadIdx.x;
    const int G   = gridDim.x;

    // Per-thread W slice in registers (block lifetime)
    float w[KPT];
#pragma unroll
    for (int k = 0; k < KPT; k++) w[k] = W_global[tid + THREADS2 * k];

    if (tid == 0) {
        mbar_init(mb0, 1);
        mbar_init(mb1, 1);
        asm volatile("fence.proxy.async.shared::cta;" ::: "memory");
    }
    __syncthreads();

    int b0 = blockIdx.x;
    if (tid == 0) {
        mbar_expect_tx(mb0, SLAB_B);
        bulk_g2s(sbuf0, conv + (size_t)b0 * SLAB, SLAB_B, mb0);
    }

    int stage = 0;
    uint32_t ph0 = 0, ph1 = 0;

    for (int b = b0; b < BATCH; b += G) {
        // Issue prefetch of next slab into the other buffer (single thread)
        int bn = b + G;
        if (bn < BATCH && tid == 0) {
            uint32_t mbn = stage ? mb0 : mb1;
            uint32_t dst = stage ? sbuf0 : sbuf1;
            mbar_expect_tx(mbn, SLAB_B);
            bulk_g2s(dst, conv + (size_t)bn * SLAB, SLAB_B, mbn);
        }

        // Wait for current slab (acquire: data visible to generic LDS)
        if (stage == 0) { mbar_wait(mb0, ph0); ph0 ^= 1; }
        else           { mbar_wait(mb1, ph1); ph1 ^= 1; }

        // Compute: linear conflict-free smem reads
        const float* cb = stage ? buf1 : buf0;
        float acc = 0.f;
#pragma unroll
        for (int k = 0; k < KPT; k++)
            acc = fmaf(cb[tid + THREADS2 * k], w[k], acc);

        // Reduce 32 partials per r (double-buffered scratch)
        float* rd = red + (stage ? THREADS2 : 0);
        rd[tid] = acc;
        __syncthreads();
        if (tid < RELC) {
            float s = 0.f;
#pragma unroll
            for (int g = 0; g < 32; g++) s += rd[tid + RELC * g];
            out[(size_t)b * RELC + tid] = s;
        }
        stage ^= 1;
    }
}

// ---------------------------------------------------------------------------
// Launch
// ---------------------------------------------------------------------------
extern "C" void kernel_launch(void* const* d_in, const int* in_sizes, int n_in,
                              void* d_out, int out_size)
{
    const float* conv = nullptr;   // 4096*1024*19 = 79691776
    const float* R    = nullptr;   // 19*1024      = 19456
    const float* U    = nullptr;   // 1024*1024    = 1048576
    for (int i = 0; i < n_in; i++) {
        switch (in_sizes[i]) {
            case 79691776: conv = (const float*)d_in[i]; break;
            case 19456:    R    = (const float*)d_in[i]; break;
            case 1048576:  U    = (const float*)d_in[i]; break;
        }
    }
    float* out = (float*)d_out;

    // Kernel 1: W = U @ R^T  (256 blocks x 4 warps, one warp per f-row)
    compute_W_kernel<<<256, 128>>>(U, R);

    // Kernel 2: persistent bulk-copy streamer
    int nsm = 148;
    cudaDeviceGetAttribute(&nsm, cudaDevAttrMultiProcessorCount, 0);
    size_t smem_bytes = (size_t)(2 * SLAB + 2 * THREADS2) * sizeof(float) + 32;
    cudaFuncSetAttribute(score_kernel, cudaFuncAttributeMaxDynamicSharedMemorySize,
                         (int)smem_bytes);
    score_kernel<<<nsm, THREADS2, smem_bytes>>>(conv, out);
}

// round 8
// speedup vs baseline: 1.1012x; 1.1012x over previous
#include <cuda_runtime.h>
#include <cuda_bf16.h>
#include <cstdint>

#define BATCH   4096
#define FILTER  1024
#define RELC    19
#define RELD    1024
#define SLAB    (FILTER * RELC)        // 19456 floats per batch row
#define HALF    (SLAB / 2)             // 9728 floats  (= 512*19, multiple of 19)
#define HALF_B  (HALF * 4)             // 38912 bytes
#define NT      608                    // 19 * 32 threads
#define KPC     16                     // f-chunks per thread per half-slab

// W[f][r] = sum_e U[f,e]*R[r,e], row-major [FILTER][RELC]
__device__ float W_global[SLAB];
// Monotonic grid-barrier counter: never reset, works across graph replays.
__device__ unsigned int g_arrive;

// ---------------------------------------------------------------------------
// mbarrier / bulk-copy helpers
// ---------------------------------------------------------------------------
__device__ __forceinline__ void mbar_init(uint32_t mbar, uint32_t count) {
    asm volatile("mbarrier.init.shared.b64 [%0], %1;" :: "r"(mbar), "r"(count) : "memory");
}
__device__ __forceinline__ void mbar_expect_tx(uint32_t mbar, uint32_t bytes) {
    asm volatile("mbarrier.arrive.expect_tx.shared.b64 _, [%0], %1;"
                 :: "r"(mbar), "r"(bytes) : "memory");
}
__device__ __forceinline__ void bulk_g2s(uint32_t dst_smem, const void* src, uint32_t bytes,
                                         uint32_t mbar) {
    asm volatile("cp.async.bulk.shared::cta.global.mbarrier::complete_tx::bytes "
                 "[%0], [%1], %2, [%3];"
                 :: "r"(dst_smem), "l"(src), "r"(bytes), "r"(mbar) : "memory");
}
__device__ __forceinline__ void mbar_wait(uint32_t mbar, uint32_t parity) {
    uint32_t done;
    asm volatile(
        "{\n\t.reg .pred p;\n\t"
        "mbarrier.try_wait.parity.acquire.cta.shared::cta.b64 p, [%1], %2;\n\t"
        "selp.b32 %0, 1, 0, p;\n\t}"
        : "=r"(done) : "r"(mbar), "r"(parity) : "memory");
    if (!done) {
        asm volatile(
            "{\n\t.reg .pred P1;\n\t"
            "W_%=:\n\t"
            "mbarrier.try_wait.parity.acquire.cta.shared::cta.b64 P1, [%0], %1, 0x989680;\n\t"
            "@P1 bra.uni D_%=;\n\t"
            "bra.uni W_%=;\n\t"
            "D_%=:\n\t}"
            :: "r"(mbar), "r"(parity) : "memory");
    }
}

// ---------------------------------------------------------------------------
// Fused persistent kernel.
//   Phase A (overlapped with first conv prefetches): distributed W = U @ R^T.
//   Grid barrier (monotonic counter, all 152 blocks co-resident).
//   Phase B: stream conv in 38KB half-slabs through a 4-deep smem ring,
//            issue-ahead-4 keeps the bulk-copy engine continuously busy.
// Index identity: slab element (tid + 608*k) has r = tid % 19 (608 = 32*19,
// HALF = 512*19), so each thread's work is linear smem reads vs W registers.
// ---------------------------------------------------------------------------
__global__ void __launch_bounds__(NT, 1)
fused_kernel(const float* __restrict__ conv, const float* __restrict__ U,
             const float* __restrict__ R, float* __restrict__ out)
{
    extern __shared__ float smem[];
    float* red = smem + 4 * HALF;                       // 2*608 floats (dbl-buffered)
    uint32_t sbase = (uint32_t)__cvta_generic_to_shared(smem);
    uint32_t mb    = sbase + (4 * HALF + 2 * NT) * 4;   // 4 mbarriers, 8B each

    const int tid  = threadIdx.x;
    const int G    = gridDim.x;
    const int b0   = blockIdx.x;
    const int warp = tid >> 5;
    const int lane = tid & 31;

    const int niter        = (BATCH - 1 - b0) / G + 1;  // slabs for this block
    const int total_chunks = 2 * niter;

    // ---- init mbarriers + prefetch first 4 half-slabs (before W phase!) ----
    if (tid == 0) {
        #pragma unroll
        for (int i = 0; i < 4; i++) mbar_init(mb + 8 * i, 1);
        asm volatile("fence.proxy.async.shared::cta;" ::: "memory");
        for (int c = 0; c < 4 && c < total_chunks; c++) {
            int b = b0 + (c >> 1) * G;
            mbar_expect_tx(mb + 8 * (c & 3), HALF_B);
            bulk_g2s(sbase + (uint32_t)(c & 3) * HALF_B,
                     conv + (size_t)b * SLAB + (size_t)(c & 1) * HALF,
                     HALF_B, mb + 8 * (c & 3));
        }
    }

    // ---- Phase A: W rows spread across ALL blocks (f = b0 + G*warp) ----
    {
        int f = b0 + G * warp;
        if (f < FILTER) {
            const float4* u4 = reinterpret_cast<const float4*>(U + (size_t)f * RELD);
            float4 u[8];
            #pragma unroll
            for (int k = 0; k < 8; k++) u[k] = u4[lane + 32 * k];

            const float4* R4 = reinterpret_cast<const float4*>(R);
            float acc[RELC];
            #pragma unroll
            for (int r = 0; r < RELC; r++) acc[r] = 0.f;
            #pragma unroll
            for (int k = 0; k < 8; k++) {
                float4 uk = u[k];
                #pragma unroll
                for (int r = 0; r < RELC; r++) {
                    float4 rv = __ldg(&R4[r * 256 + lane + 32 * k]);
                    acc[r] += uk.x * rv.x + uk.y * rv.y + uk.z * rv.z + uk.w * rv.w;
                }
            }
            #pragma unroll
            for (int o = 16; o > 0; o >>= 1)
                #pragma unroll
                for (int r = 0; r < RELC; r++)
                    acc[r] += __shfl_xor_sync(0xFFFFFFFFu, acc[r], o);
            if (lane == 0) {
                #pragma unroll
                for (int r = 0; r < RELC; r++)
                    W_global[f * RELC + r] = acc[r];
            }
        }
    }

    // ---- grid barrier (monotonic counter: replay-safe without reset) ----
    __threadfence();          // publish W writes
    __syncthreads();          // whole block's W done before arriving
    if (tid == 0) {
        unsigned int old = atomicAdd(&g_arrive, 1u);
        unsigned int tgt = (old / (unsigned)G + 1u) * (unsigned)G;
        while (*((volatile unsigned int*)&g_arrive) < tgt) __nanosleep(64);
        __threadfence();      // acquire: other blocks' W visible
    }
    __syncthreads();

    // ---- per-thread W slice in registers ----
    float w[2 * KPC];
    #pragma unroll
    for (int k = 0; k < 2 * KPC; k++) w[k] = W_global[tid + NT * k];

    // ---- Phase B: streaming loop over half-slab chunks ----
    float acc = 0.f;
    for (int c = 0; c < total_chunks; c++) {
        const int      buf = c & 3;
        const uint32_t par = (c >> 2) & 1;
        mbar_wait(mb + 8 * buf, par);

        const float* cb = smem + buf * HALF;
        const int    wo = (c & 1) * KPC;
        #pragma unroll
        for (int k = 0; k < KPC; k++)
            acc = fmaf(cb[tid + NT * k], w[wo + k], acc);

        if (c & 1) {
            // end of slab: publish partials, then reduce 32 -> 1 per r
            float* rd = red + ((c >> 1) & 1) * NT;
            rd[tid] = acc;
            __syncthreads();                         // frees buffer, red visible
            if (tid == 0 && c + 4 < total_chunks) {  // refill freed buffer
                int cn = c + 4, b = b0 + (cn >> 1) * G;
                mbar_expect_tx(mb + 8 * (cn & 3), HALF_B);
                bulk_g2s(sbase + (uint32_t)(cn & 3) * HALF_B,
                         conv + (size_t)b * SLAB + (size_t)(cn & 1) * HALF,
                         HALF_B, mb + 8 * (cn & 3));
            }
            if (tid < RELC) {
                float s = 0.f;
                #pragma unroll
                for (int g = 0; g < 32; g++) s += rd[tid + RELC * g];
                out[(size_t)(b0 + (c >> 1) * G) * RELC + tid] = s;
            }
            acc = 0.f;
        } else {
            __syncthreads();                         // all done reading chunk c
            if (tid == 0 && c + 4 < total_chunks) {
                int cn = c + 4, b = b0 + (cn >> 1) * G;
                mbar_expect_tx(mb + 8 * (cn & 3), HALF_B);
                bulk_g2s(sbase + (uint32_t)(cn & 3) * HALF_B,
                         conv + (size_t)b * SLAB + (size_t)(cn & 1) * HALF,
                         HALF_B, mb + 8 * (cn & 3));
            }
        }
    }
}

// ---------------------------------------------------------------------------
// Launch: single fused kernel
// ---------------------------------------------------------------------------
extern "C" void kernel_launch(void* const* d_in, const int* in_sizes, int n_in,
                              void* d_out, int out_size)
{
    const float* conv = nullptr;   // 4096*1024*19 = 79691776
    const float* R    = nullptr;   // 19*1024      = 19456
    const float* U    = nullptr;   // 1024*1024    = 1048576
    for (int i = 0; i < n_in; i++) {
        switch (in_sizes[i]) {
            case 79691776: conv = (const float*)d_in[i]; break;
            case 19456:    R    = (const float*)d_in[i]; break;
            case 1048576:  U    = (const float*)d_in[i]; break;
        }
    }
    float* out = (float*)d_out;

    int nsm = 148;
    cudaDeviceGetAttribute(&nsm, cudaDevAttrMultiProcessorCount, 0);

    // 4 half-slab buffers + dbl-buffered red scratch + 4 mbarriers
    size_t smem_bytes = (size_t)(4 * HALF + 2 * NT) * sizeof(float) + 32;  // 160544 B
    cudaFuncSetAttribute(fused_kernel, cudaFuncAttributeMaxDynamicSharedMemorySize,
                         (int)smem_bytes);
    fused_kernel<<<nsm, NT, smem_bytes>>>(conv, U, R, out);
}

// round 10
// speedup vs baseline: 1.2735x; 1.1565x over previous
#include <cuda_runtime.h>
#include <cuda_bf16.h>
#include <cstdint>

#define BATCH   4096
#define FILTER  1024
#define RELC    19
#define RELD    1024
#define SLAB    (FILTER * RELC)        // 19456 floats per batch row
#define HALF    (SLAB / 2)             // 9728 floats (= 512*19)
#define HALF_B  (HALF * 4)             // 38912 bytes
#define NT      608                    // 19 * 32 threads
#define KPC     16                     // f-chunks per thread per half-slab
#define NBUF    5                      // ring depth (odd: decouples from chunk parity)

// W[f][r] = sum_e U[f,e]*R[r,e], row-major [FILTER][RELC]
__device__ float W_global[SLAB];
// Monotonic grid-barrier counter: never reset, replay-safe (each launch adds
// exactly gridDim.x, so it is always a multiple of G at launch entry).
__device__ unsigned int g_arrive;

// ---------------------------------------------------------------------------
// mbarrier / bulk-copy helpers
// ---------------------------------------------------------------------------
__device__ __forceinline__ void mbar_init(uint32_t mbar, uint32_t count) {
    asm volatile("mbarrier.init.shared.b64 [%0], %1;" :: "r"(mbar), "r"(count) : "memory");
}
__device__ __forceinline__ void mbar_expect_tx(uint32_t mbar, uint32_t bytes) {
    asm volatile("mbarrier.arrive.expect_tx.shared.b64 _, [%0], %1;"
                 :: "r"(mbar), "r"(bytes) : "memory");
}
__device__ __forceinline__ void bulk_g2s(uint32_t dst_smem, const void* src, uint32_t bytes,
                                         uint32_t mbar) {
    asm volatile("cp.async.bulk.shared::cta.global.mbarrier::complete_tx::bytes "
                 "[%0], [%1], %2, [%3];"
                 :: "r"(dst_smem), "l"(src), "r"(bytes), "r"(mbar) : "memory");
}
__device__ __forceinline__ void mbar_wait(uint32_t mbar, uint32_t parity) {
    uint32_t done;
    asm volatile(
        "{\n\t.reg .pred p;\n\t"
        "mbarrier.try_wait.parity.acquire.cta.shared::cta.b64 p, [%1], %2;\n\t"
        "selp.b32 %0, 1, 0, p;\n\t}"
        : "=r"(done) : "r"(mbar), "r"(parity) : "memory");
    if (!done) {
        asm volatile(
            "{\n\t.reg .pred P1;\n\t"
            "W_%=:\n\t"
            "mbarrier.try_wait.parity.acquire.cta.shared::cta.b64 P1, [%0], %1, 0x989680;\n\t"
            "@P1 bra.uni D_%=;\n\t"
            "bra.uni W_%=;\n\t"
            "D_%=:\n\t}"
            :: "r"(mbar), "r"(parity) : "memory");
    }
}

// ---------------------------------------------------------------------------
// Fused persistent kernel.
//   Prologue: issue NBUF half-slab bulk copies (engine streams during phase A).
//   Phase A: distributed W = U @ R^T (one warp per f-row across all blocks).
//   Grid barrier (monotonic counter; all 152 CTAs co-resident at 1 CTA/SM).
//   Phase B: per-slab loop — consume even chunk (w[0..15], compile-time
//            indices only), consume odd chunk (w[16..31]), ONE syncthreads,
//            then tid0 batch-refills the two freed ring buffers. The ring
//            backlog (~3-5 chunks) keeps the bulk-copy engine always busy.
// Index identity: slab element (tid + 608*k) has r = tid % 19 (608 = 32*19,
// HALF = 512*19), so per-thread work is linear conflict-free smem reads
// against W values held in registers.
// ---------------------------------------------------------------------------
__global__ void __launch_bounds__(NT, 1)
fused_kernel(const float* __restrict__ conv, const float* __restrict__ U,
             const float* __restrict__ R, float* __restrict__ out)
{
    extern __shared__ float smem[];
    float* red = smem + NBUF * HALF;                         // 2*608 floats
    uint32_t sbase = (uint32_t)__cvta_generic_to_shared(smem);
    uint32_t mb    = sbase + (NBUF * HALF + 2 * NT) * 4;     // NBUF mbarriers (8B each)

    const int tid  = threadIdx.x;
    const int G    = gridDim.x;
    const int b0   = blockIdx.x;
    const int warp = tid >> 5;
    const int lane = tid & 31;

    const int niter        = (BATCH - 1 - b0) / G + 1;       // slabs for this block
    const int total_chunks = 2 * niter;                      // >= 52 for G<=2048

    // ---- init mbarriers + prefetch first NBUF half-slabs (before W phase) ----
    if (tid == 0) {
        #pragma unroll
        for (int i = 0; i < NBUF; i++) mbar_init(mb + 8 * i, 1);
        asm volatile("fence.proxy.async.shared::cta;" ::: "memory");
        #pragma unroll
        for (int c = 0; c < NBUF; c++) {
            if (c < total_chunks) {
                int b = b0 + (c >> 1) * G;
                mbar_expect_tx(mb + 8 * c, HALF_B);
                bulk_g2s(sbase + (uint32_t)c * HALF_B,
                         conv + (size_t)b * SLAB + (size_t)(c & 1) * HALF,
                         HALF_B, mb + 8 * c);
            }
        }
    }

    // ---- Phase A: W rows spread across ALL blocks (f = b0 + G*warp) ----
    {
        int f = b0 + G * warp;
        if (f < FILTER) {
            const float4* u4 = reinterpret_cast<const float4*>(U + (size_t)f * RELD);
            float4 u[8];
            #pragma unroll
            for (int k = 0; k < 8; k++) u[k] = u4[lane + 32 * k];

            const float4* R4 = reinterpret_cast<const float4*>(R);
            float acc[RELC];
            #pragma unroll
            for (int r = 0; r < RELC; r++) acc[r] = 0.f;
            #pragma unroll
            for (int k = 0; k < 8; k++) {
                float4 uk = u[k];
                #pragma unroll
                for (int r = 0; r < RELC; r++) {
                    float4 rv = __ldg(&R4[r * 256 + lane + 32 * k]);
                    acc[r] += uk.x * rv.x + uk.y * rv.y + uk.z * rv.z + uk.w * rv.w;
                }
            }
            #pragma unroll
            for (int o = 16; o > 0; o >>= 1)
                #pragma unroll
                for (int r = 0; r < RELC; r++)
                    acc[r] += __shfl_xor_sync(0xFFFFFFFFu, acc[r], o);
            if (lane == 0) {
                #pragma unroll
                for (int r = 0; r < RELC; r++)
                    W_global[f * RELC + r] = acc[r];
            }
        }
    }

    // ---- grid barrier (monotonic counter: replay-safe, no reset) ----
    __threadfence();          // publish this block's W rows
    __syncthreads();          // all warps' W done before arriving
    if (tid == 0) {
        unsigned int old = atomicAdd(&g_arrive, 1u);
        unsigned int tgt = (old / (unsigned)G + 1u) * (unsigned)G;
        while (*((volatile unsigned int*)&g_arrive) < tgt) __nanosleep(64);
        __threadfence();      // acquire: other blocks' W visible
    }
    __syncthreads();

    // ---- per-thread W slice in registers (compile-time indices ONLY below) ----
    float w[2 * KPC];
    #pragma unroll
    for (int k = 0; k < 2 * KPC; k++) w[k] = W_global[tid + NT * k];

    // ---- Phase B: per-slab streaming loop ----
    int      cons_buf   = 0;         // ring position of next chunk to consume
    uint32_t cons_par   = 0;         // its expected mbarrier parity
    int      iss_buf    = 0;         // ring position receiving chunk `next_issue`
    int      next_issue = NBUF;

    for (int s = 0; s < niter; s++) {
        // -- even chunk: w[0..15] (static indices) --
        mbar_wait(mb + 8 * cons_buf, cons_par);
        const float* cb = smem + cons_buf * HALF;
        float acc = 0.f;
        #pragma unroll
        for (int k = 0; k < KPC; k++)
            acc = fmaf(cb[tid + NT * k], w[k], acc);
        if (++cons_buf == NBUF) { cons_buf = 0; cons_par ^= 1; }

        // -- odd chunk: w[16..31] (static indices) --
        mbar_wait(mb + 8 * cons_buf, cons_par);
        cb = smem + cons_buf * HALF;
        #pragma unroll
        for (int k = 0; k < KPC; k++)
            acc = fmaf(cb[tid + NT * k], w[KPC + k], acc);
        if (++cons_buf == NBUF) { cons_buf = 0; cons_par ^= 1; }

        // -- publish partials; ONE sync per slab (red dbl-buffered by s&1) --
        float* rd = red + (s & 1) * NT;
        rd[tid] = acc;
        __syncthreads();               // both chunk buffers free + red visible

        // -- batch-refill the two freed ring buffers --
        if (tid == 0) {
            #pragma unroll
            for (int j = 0; j < 2; j++) {
                if (next_issue < total_chunks) {
                    int b = b0 + (next_issue >> 1) * G;
                    mbar_expect_tx(mb + 8 * iss_buf, HALF_B);
                    bulk_g2s(sbase + (uint32_t)iss_buf * HALF_B,
                             conv + (size_t)b * SLAB + (size_t)(next_issue & 1) * HALF,
                             HALF_B, mb + 8 * iss_buf);
                    next_issue++;
                    if (++iss_buf == NBUF) iss_buf = 0;
                }
            }
        }

        // -- final 32 -> 1 reduction per r, write scores --
        if (tid < RELC) {
            float sum = 0.f;
            #pragma unroll
            for (int g = 0; g < 32; g++) sum += rd[tid + RELC * g];
            out[(size_t)(b0 + s * G) * RELC + tid] = sum;
        }
    }
}

// ---------------------------------------------------------------------------
// Launch: single fused kernel
// ---------------------------------------------------------------------------
extern "C" void kernel_launch(void* const* d_in, const int* in_sizes, int n_in,
                              void* d_out, int out_size)
{
    const float* conv = nullptr;   // 4096*1024*19 = 79691776
    const float* R    = nullptr;   // 19*1024      = 19456
    const float* U    = nullptr;   // 1024*1024    = 1048576
    for (int i = 0; i < n_in; i++) {
        switch (in_sizes[i]) {
            case 79691776: conv = (const float*)d_in[i]; break;
            case 19456:    R    = (const float*)d_in[i]; break;
            case 1048576:  U    = (const float*)d_in[i]; break;
        }
    }
    float* out = (float*)d_out;

    int nsm = 148;
    cudaDeviceGetAttribute(&nsm, cudaDevAttrMultiProcessorCount, 0);

    // NBUF half-slab buffers + dbl-buffered red scratch + NBUF mbarriers
    size_t smem_bytes = (size_t)(NBUF * HALF + 2 * NT) * sizeof(float) + NBUF * 8;
    cudaFuncSetAttribute(fused_kernel, cudaFuncAttributeMaxDynamicSharedMemorySize,
                         (int)smem_bytes);
    fused_kernel<<<nsm, NT, smem_bytes>>>(conv, U, R, out);
}

// round 13
// speedup vs baseline: 1.3678x; 1.0740x over previous
#include <cuda_runtime.h>
#include <cuda_bf16.h>
#include <cstdint>

#define BATCH   4096
#define FILTER  1024
#define RELC    19
#define RELD    1024
#define SLAB    (FILTER * RELC)        // 19456 floats per batch row
#define HALF    (SLAB / 2)             // 9728 floats (= 512*19)
#define HALF_B  (HALF * 4)             // 38912 bytes
#define NT      608                    // 19 * 32 threads
#define KPC     16                     // f-chunks per thread per half-slab
#define NBUF    5                      // ring depth

// W[f][r] = sum_e U[f,e]*R[r,e], row-major [FILTER][RELC]
__device__ float W_global[SLAB];
// Monotonic grid-barrier counter: never reset, replay-safe.
__device__ unsigned int g_arrive;

// ---------------------------------------------------------------------------
// mbarrier / bulk-copy helpers
// ---------------------------------------------------------------------------
__device__ __forceinline__ void mbar_init(uint32_t mbar, uint32_t count) {
    asm volatile("mbarrier.init.shared.b64 [%0], %1;" :: "r"(mbar), "r"(count) : "memory");
}
__device__ __forceinline__ void mbar_expect_tx(uint32_t mbar, uint32_t bytes) {
    asm volatile("mbarrier.arrive.expect_tx.shared.b64 _, [%0], %1;"
                 :: "r"(mbar), "r"(bytes) : "memory");
}
__device__ __forceinline__ void bulk_g2s(uint32_t dst_smem, const void* src, uint32_t bytes,
                                         uint32_t mbar) {
    asm volatile("cp.async.bulk.shared::cta.global.mbarrier::complete_tx::bytes "
                 "[%0], [%1], %2, [%3];"
                 :: "r"(dst_smem), "l"(src), "r"(bytes), "r"(mbar) : "memory");
}
__device__ __forceinline__ void mbar_wait(uint32_t mbar, uint32_t parity) {
    uint32_t done;
    asm volatile(
        "{\n\t.reg .pred p;\n\t"
        "mbarrier.try_wait.parity.acquire.cta.shared::cta.b64 p, [%1], %2;\n\t"
        "selp.b32 %0, 1, 0, p;\n\t}"
        : "=r"(done) : "r"(mbar), "r"(parity) : "memory");
    if (!done) {
        asm volatile(
            "{\n\t.reg .pred P1;\n\t"
            "W_%=:\n\t"
            "mbarrier.try_wait.parity.acquire.cta.shared::cta.b64 P1, [%0], %1, 0x989680;\n\t"
            "@P1 bra.uni D_%=;\n\t"
            "bra.uni W_%=;\n\t"
            "D_%=:\n\t}"
            :: "r"(mbar), "r"(parity) : "memory");
    }
}

// ---------------------------------------------------------------------------
// Fused persistent kernel.
//   Prologue (tid0): init 6 mbarriers; bulk-copy R (76KB) into ring buffers
//     3+4 (exactly 2 x 38912 B); bulk-copy conv chunks 0-2 into buffers 0-2.
//   Phase A: W = U @ R^T with R read from SMEM (kills the 81MB L2 storm that
//     cost ~12.8us of chip bandwidth-time in the previous round; R now costs
//     11.6MB chip-wide). One warp per f-row, f = b0 + G*warp.
//   After phase A: syncthreads (R dead) -> tid0 issues conv chunks 3,4 into
//     buffers 3,4 (engine works through the grid-barrier skew) -> grid
//     barrier -> load per-thread W slice into registers.
//   Phase B: identical 5-deep ring streamer: per slab consume 2 chunks with
//     compile-time w[] indices, ONE syncthreads, batch-refill 2 buffers.
// Index identity: slab element (tid + 608*k) has r = tid % 19, so per-thread
// work is linear conflict-free smem reads against W registers.
// ---------------------------------------------------------------------------
__global__ void __launch_bounds__(NT, 1)
fused_kernel(const float* __restrict__ conv, const float* __restrict__ U,
             const float* __restrict__ R, float* __restrict__ out)
{
    extern __shared__ float smem[];
    float* red = smem + NBUF * HALF;                         // 2*608 floats
    uint32_t sbase = (uint32_t)__cvta_generic_to_shared(smem);
    uint32_t mb    = sbase + (NBUF * HALF + 2 * NT) * 4;     // 5 ring mbars + 1 R mbar
    uint32_t mb_R  = mb + 8 * NBUF;

    const int tid  = threadIdx.x;
    const int G    = gridDim.x;
    const int b0   = blockIdx.x;
    const int warp = tid >> 5;
    const int lane = tid & 31;

    const int niter        = (BATCH - 1 - b0) / G + 1;       // slabs for this block
    const int total_chunks = 2 * niter;                      // >= 52

    // ---- prologue: mbarriers, R stage, conv chunks 0-2 ----
    if (tid == 0) {
        #pragma unroll
        for (int i = 0; i <= NBUF; i++) mbar_init(mb + 8 * i, 1);
        asm volatile("fence.proxy.async.shared::cta;" ::: "memory");
        // R -> ring buffers 3,4 (76KB = 2*HALF_B exactly)
        mbar_expect_tx(mb_R, 2 * HALF_B);
        bulk_g2s(sbase + (uint32_t)3 * HALF_B, R, 2 * HALF_B, mb_R);
        // conv chunks 0,1,2 -> buffers 0,1,2
        #pragma unroll
        for (int c = 0; c < 3; c++) {
            int b = b0 + (c >> 1) * G;
            mbar_expect_tx(mb + 8 * c, HALF_B);
            bulk_g2s(sbase + (uint32_t)c * HALF_B,
                     conv + (size_t)b * SLAB + (size_t)(c & 1) * HALF,
                     HALF_B, mb + 8 * c);
        }
    }
    __syncthreads();               // mbarrier init visible to all waiters

    // ---- Phase A: W rows, R read from SMEM ----
    mbar_wait(mb_R, 0);            // acquire: R tile visible for LDS
    {
        int f = b0 + G * warp;
        if (f < FILTER) {
            const float4* u4 = reinterpret_cast<const float4*>(U + (size_t)f * RELD);
            float4 u[8];
            #pragma unroll
            for (int k = 0; k < 8; k++) u[k] = __ldg(&u4[lane + 32 * k]);

            const float4* Rs4 = reinterpret_cast<const float4*>(smem + 3 * HALF);
            float acc[RELC];
            #pragma unroll
            for (int r = 0; r < RELC; r++) acc[r] = 0.f;
            #pragma unroll
            for (int k = 0; k < 8; k++) {
                float4 uk = u[k];
                #pragma unroll
                for (int r = 0; r < RELC; r++) {
                    float4 rv = Rs4[r * 256 + lane + 32 * k];
                    acc[r] += uk.x * rv.x + uk.y * rv.y + uk.z * rv.z + uk.w * rv.w;
                }
            }
            #pragma unroll
            for (int o = 16; o > 0; o >>= 1)
                #pragma unroll
                for (int r = 0; r < RELC; r++)
                    acc[r] += __shfl_xor_sync(0xFFFFFFFFu, acc[r], o);
            if (lane == 0) {
                #pragma unroll
                for (int r = 0; r < RELC; r++)
                    W_global[f * RELC + r] = acc[r];
            }
        }
    }

    __threadfence();               // publish W rows
    __syncthreads();               // all warps done reading R (buffers 3,4 free)

    // Refill buffers 3,4 with conv chunks 3,4 BEFORE the grid barrier:
    // the copy engine streams through the barrier skew.
    if (tid == 0) {
        #pragma unroll
        for (int c = 3; c < 5; c++) {
            int b = b0 + (c >> 1) * G;
            mbar_expect_tx(mb + 8 * c, HALF_B);
            bulk_g2s(sbase + (uint32_t)c * HALF_B,
                     conv + (size_t)b * SLAB + (size_t)(c & 1) * HALF,
                     HALF_B, mb + 8 * c);
        }
        // grid barrier (monotonic counter: replay-safe, no reset)
        unsigned int old = atomicAdd(&g_arrive, 1u);
        unsigned int tgt = (old / (unsigned)G + 1u) * (unsigned)G;
        while (*((volatile unsigned int*)&g_arrive) < tgt) __nanosleep(64);
        __threadfence();           // acquire: other blocks' W visible
    }
    __syncthreads();

    // ---- per-thread W slice in registers (compile-time indices ONLY below) ----
    float w[2 * KPC];
    #pragma unroll
    for (int k = 0; k < 2 * KPC; k++) w[k] = W_global[tid + NT * k];

    // ---- Phase B: per-slab streaming loop over the 5-deep ring ----
    int      cons_buf   = 0;
    uint32_t cons_par   = 0;
    int      iss_buf    = 0;
    int      next_issue = NBUF;

    for (int s = 0; s < niter; s++) {
        // -- even chunk: w[0..15] --
        mbar_wait(mb + 8 * cons_buf, cons_par);
        const float* cb = smem + cons_buf * HALF;
        float acc = 0.f;
        #pragma unroll
        for (int k = 0; k < KPC; k++)
            acc = fmaf(cb[tid + NT * k], w[k], acc);
        if (++cons_buf == NBUF) { cons_buf = 0; cons_par ^= 1; }

        // -- odd chunk: w[16..31] --
        mbar_wait(mb + 8 * cons_buf, cons_par);
        cb = smem + cons_buf * HALF;
        #pragma unroll
        for (int k = 0; k < KPC; k++)
            acc = fmaf(cb[tid + NT * k], w[KPC + k], acc);
        if (++cons_buf == NBUF) { cons_buf = 0; cons_par ^= 1; }

        // -- publish partials; ONE sync per slab (red dbl-buffered by s&1) --
        float* rd = red + (s & 1) * NT;
        rd[tid] = acc;
        __syncthreads();           // both chunk buffers free + red visible

        // -- batch-refill the two freed ring buffers --
        if (tid == 0) {
            #pragma unroll
            for (int j = 0; j < 2; j++) {
                if (next_issue < total_chunks) {
                    int b = b0 + (next_issue >> 1) * G;
                    mbar_expect_tx(mb + 8 * iss_buf, HALF_B);
                    bulk_g2s(sbase + (uint32_t)iss_buf * HALF_B,
                             conv + (size_t)b * SLAB + (size_t)(next_issue & 1) * HALF,
                             HALF_B, mb + 8 * iss_buf);
                    next_issue++;
                    if (++iss_buf == NBUF) iss_buf = 0;
                }
            }
        }

        // -- final 32 -> 1 reduction per r, write scores --
        if (tid < RELC) {
            float sum = 0.f;
            #pragma unroll
            for (int g = 0; g < 32; g++) sum += rd[tid + RELC * g];
            out[(size_t)(b0 + s * G) * RELC + tid] = sum;
        }
    }
}

// ---------------------------------------------------------------------------
// Launch: single fused kernel
// ---------------------------------------------------------------------------
extern "C" void kernel_launch(void* const* d_in, const int* in_sizes, int n_in,
                              void* d_out, int out_size)
{
    const float* conv = nullptr;   // 4096*1024*19 = 79691776
    const float* R    = nullptr;   // 19*1024      = 19456
    const float* U    = nullptr;   // 1024*1024    = 1048576
    for (int i = 0; i < n_in; i++) {
        switch (in_sizes[i]) {
            case 79691776: conv = (const float*)d_in[i]; break;
            case 19456:    R    = (const float*)d_in[i]; break;
            case 1048576:  U    = (const float*)d_in[i]; break;
        }
    }
    float* out = (float*)d_out;

    int nsm = 148;
    cudaDeviceGetAttribute(&nsm, cudaDevAttrMultiProcessorCount, 0);

    // 5 ring buffers + dbl-buffered red scratch + 6 mbarriers
    size_t smem_bytes = (size_t)(NBUF * HALF + 2 * NT) * sizeof(float) + (NBUF + 1) * 8;
    cudaFuncSetAttribute(fused_kernel, cudaFuncAttributeMaxDynamicSharedMemorySize,
                         (int)smem_bytes);
    fused_kernel<<<nsm, NT, smem_bytes>>>(conv, U, R, out);
}